// round 2
// baseline (speedup 1.0000x reference)
#include <cuda_runtime.h>

// Problem constants (target: [B, T, L] float32)
constexpr int B_ = 32;
constexpr int T_ = 8;
constexpr int L_ = 256;
constexpr int TILE = 128;   // output quadrant per block

// source[b, l1, l2] = (1/(T*L)) * sum_t sum_n x[n] * x[n-l1] * x[n-l2]
// with x[k] = 0 for k < 0 (zero left padding).
//
// Grid: (4, 32) — blockIdx.x selects the 128x128 quadrant, blockIdx.y = batch.
// Block: 256 threads, each owning an 8x8 register tile in a STRIDED layout
// (l = base + lane + 16*r) so shared loads are bank-conflict free.
__global__ __launch_bounds__(256, 1)
void bispectrum_kernel(const float* __restrict__ tgt, float* __restrict__ out)
{
    __shared__ float xs[2 * L_];   // [0..255] = 0 pad, [256..511] = x[t]

    const int b  = blockIdx.y;
    const int q  = blockIdx.x;
    const int l1_base = (q >> 1) * TILE;
    const int l2_base = (q & 1)  * TILE;

    const int tid = threadIdx.x;
    const int tx  = tid & 15;   // 16 lanes -> l2 strided
    const int ty  = tid >> 4;   // 16 rows  -> l1 strided

    float acc[8][8];
#pragma unroll
    for (int i = 0; i < 8; i++)
#pragma unroll
        for (int j = 0; j < 8; j++) acc[i][j] = 0.0f;

    // Base offsets: xa[i] = xs[ba0 + n - 16*i], xb[j] = xs[bb0 + n - 16*j]
    const int ba0 = L_ - l1_base - ty;
    const int bb0 = L_ - l2_base - tx;

    for (int t = 0; t < T_; t++) {
        __syncthreads();
        xs[tid]       = 0.0f;
        xs[L_ + tid]  = tgt[(b * T_ + t) * L_ + tid];
        __syncthreads();

#pragma unroll 2
        for (int n = 0; n < L_; n++) {
            const float xn = xs[L_ + n];

            float xa[8], xb[8], p[8];
#pragma unroll
            for (int i = 0; i < 8; i++) xa[i] = xs[ba0 + n - 16 * i];
#pragma unroll
            for (int j = 0; j < 8; j++) xb[j] = xs[bb0 + n - 16 * j];
#pragma unroll
            for (int i = 0; i < 8; i++) p[i] = xn * xa[i];

#pragma unroll
            for (int i = 0; i < 8; i++)
#pragma unroll
                for (int j = 0; j < 8; j++)
                    acc[i][j] = fmaf(p[i], xb[j], acc[i][j]);
        }
    }

    const float scale = 1.0f / (float)(T_ * L_);
    float* ob = out + (size_t)b * L_ * L_;
#pragma unroll
    for (int i = 0; i < 8; i++) {
        const int l1 = l1_base + ty + 16 * i;
#pragma unroll
        for (int j = 0; j < 8; j++) {
            const int l2 = l2_base + tx + 16 * j;
            ob[l1 * L_ + l2] = acc[i][j] * scale;
        }
    }
}

extern "C" void kernel_launch(void* const* d_in, const int* in_sizes, int n_in,
                              void* d_out, int out_size)
{
    const float* tgt = (const float*)d_in[0];
    float* out = (float*)d_out;

    dim3 grid(4, B_);
    bispectrum_kernel<<<grid, 256>>>(tgt, out);

    // Reference returns (source, target): echo target after source if the
    // output buffer holds both.
    const long long src_elems = (long long)B_ * L_ * L_;        // 2,097,152
    const long long tgt_elems = (long long)B_ * T_ * L_;        // 65,536
    if ((long long)out_size >= src_elems + tgt_elems) {
        cudaMemcpyAsync(out + src_elems, tgt, sizeof(float) * tgt_elems,
                        cudaMemcpyDeviceToDevice);
    }
}

// round 3
// speedup vs baseline: 1.0074x; 1.0074x over previous
#include <cuda_runtime.h>

// Problem constants (target: [B, T, L] float32)
constexpr int B_ = 32;
constexpr int T_ = 8;
constexpr int L_ = 256;
constexpr int TILE = 128;   // output quadrant per block

// source[b, l1, l2] = (1/(T*L)) * sum_t sum_n x[n] * x[n-l1] * x[n-l2]
// with x[k] = 0 for k < 0 (zero left padding).
//
// Grid: (4, 32) — blockIdx.x selects the 128x128 quadrant, blockIdx.y = batch.
// Block: 256 threads, each owning an 8x8 register tile in a STRIDED layout
// (l = base + lane + 16*r) so shared loads are bank-conflict free.
__global__ __launch_bounds__(256, 1)
void bispectrum_kernel(const float* __restrict__ tgt, float* __restrict__ out)
{
    __shared__ float xs[2 * L_];   // [0..255] = 0 pad, [256..511] = x[t]

    const int b  = blockIdx.y;
    const int q  = blockIdx.x;
    const int l1_base = (q >> 1) * TILE;
    const int l2_base = (q & 1)  * TILE;

    const int tid = threadIdx.x;
    const int tx  = tid & 15;   // 16 lanes -> l2 strided
    const int ty  = tid >> 4;   // 16 rows  -> l1 strided

    float acc[8][8];
#pragma unroll
    for (int i = 0; i < 8; i++)
#pragma unroll
        for (int j = 0; j < 8; j++) acc[i][j] = 0.0f;

    // Base offsets: xa[i] = xs[ba0 + n - 16*i], xb[j] = xs[bb0 + n - 16*j]
    const int ba0 = L_ - l1_base - ty;
    const int bb0 = L_ - l2_base - tx;

    for (int t = 0; t < T_; t++) {
        __syncthreads();
        xs[tid]       = 0.0f;
        xs[L_ + tid]  = tgt[(b * T_ + t) * L_ + tid];
        __syncthreads();

#pragma unroll 2
        for (int n = 0; n < L_; n++) {
            const float xn = xs[L_ + n];

            float xa[8], xb[8], p[8];
#pragma unroll
            for (int i = 0; i < 8; i++) xa[i] = xs[ba0 + n - 16 * i];
#pragma unroll
            for (int j = 0; j < 8; j++) xb[j] = xs[bb0 + n - 16 * j];
#pragma unroll
            for (int i = 0; i < 8; i++) p[i] = xn * xa[i];

#pragma unroll
            for (int i = 0; i < 8; i++)
#pragma unroll
                for (int j = 0; j < 8; j++)
                    acc[i][j] = fmaf(p[i], xb[j], acc[i][j]);
        }
    }

    const float scale = 1.0f / (float)(T_ * L_);
    float* ob = out + (size_t)b * L_ * L_;
#pragma unroll
    for (int i = 0; i < 8; i++) {
        const int l1 = l1_base + ty + 16 * i;
#pragma unroll
        for (int j = 0; j < 8; j++) {
            const int l2 = l2_base + tx + 16 * j;
            ob[l1 * L_ + l2] = acc[i][j] * scale;
        }
    }
}

extern "C" void kernel_launch(void* const* d_in, const int* in_sizes, int n_in,
                              void* d_out, int out_size)
{
    const float* tgt = (const float*)d_in[0];
    float* out = (float*)d_out;

    dim3 grid(4, B_);
    bispectrum_kernel<<<grid, 256>>>(tgt, out);

    // Reference returns (source, target): echo target after source if the
    // output buffer holds both.
    const long long src_elems = (long long)B_ * L_ * L_;        // 2,097,152
    const long long tgt_elems = (long long)B_ * T_ * L_;        // 65,536
    if ((long long)out_size >= src_elems + tgt_elems) {
        cudaMemcpyAsync(out + src_elems, tgt, sizeof(float) * tgt_elems,
                        cudaMemcpyDeviceToDevice);
    }
}

// round 4
// speedup vs baseline: 1.0675x; 1.0596x over previous
#include <cuda_runtime.h>

// Problem constants (target: [B, T, L] float32)
constexpr int B_ = 32;
constexpr int T_ = 8;
constexpr int L_ = 256;
constexpr int TILE = 128;   // output quadrant per block

// source[b, l1, l2] = (1/(T*L)) * sum_t sum_n x[n] * x[n-l1] * x[n-l2],
// x[k] = 0 for k < 0.
//
// f32x2-packed version: each thread owns an 8x8 tile, accumulated as
// 4 (l1-pairs) x 8 (l2) packed f32x2 registers. fma.rn.f32x2 does 2 FMAs
// per fma-pipe issue slot (rt_SMSP=2 is the FFMA ceiling we hit before).
//
// Replicated operands ((xn,xn) and (xb,xb)) are loaded as single LDS.64
// from a DUPLICATED shared copy of the padded signal (xd[2k]=xd[2k+1]=x[k]),
// whose even indices keep 8-byte alignment — no replication MOVs.

__device__ __forceinline__ unsigned long long pack2(float lo, float hi) {
    unsigned long long r;
    asm("mov.b64 %0, {%1, %2};" : "=l"(r) : "f"(lo), "f"(hi));
    return r;
}
__device__ __forceinline__ void unpack2(unsigned long long v, float& lo, float& hi) {
    asm("mov.b64 {%0, %1}, %2;" : "=f"(lo), "=f"(hi) : "l"(v));
}
__device__ __forceinline__ void fma2(unsigned long long& d,
                                     unsigned long long a, unsigned long long b) {
    asm("fma.rn.f32x2 %0, %1, %2, %0;" : "+l"(d) : "l"(a), "l"(b));
}
__device__ __forceinline__ unsigned long long mul2(unsigned long long a,
                                                   unsigned long long b) {
    unsigned long long r;
    asm("mul.rn.f32x2 %0, %1, %2;" : "=l"(r) : "l"(a), "l"(b));
    return r;
}

__global__ __launch_bounds__(256, 1)
void bispectrum_kernel(const float* __restrict__ tgt, float* __restrict__ out)
{
    __shared__ float xs[2 * L_];                    // plain padded: [0..255]=0, [256..511]=x
    __shared__ __align__(16) float xd[4 * L_];      // duplicated padded: xd[2k]=xd[2k+1]=xs[k]

    const int b  = blockIdx.y;
    const int q  = blockIdx.x;
    const int l1_base = (q >> 1) * TILE;
    const int l2_base = (q & 1)  * TILE;

    const int tid = threadIdx.x;
    const int tx  = tid & 15;   // l2 = l2_base + tx + 16*j
    const int ty  = tid >> 4;   // l1 = l1_base + 2*ty + 32*ip + {0,1}

    const int l1off = l1_base + 2 * ty;

    unsigned long long acc2[4][8];
#pragma unroll
    for (int ip = 0; ip < 4; ip++)
#pragma unroll
        for (int j = 0; j < 8; j++) acc2[ip][j] = 0ull;

    for (int t = 0; t < T_; t++) {
        __syncthreads();
        const float v = tgt[(b * T_ + t) * L_ + tid];
        xs[tid]              = 0.0f;
        xs[L_ + tid]         = v;
        xd[2 * tid]          = 0.0f;
        xd[2 * tid + 1]      = 0.0f;
        xd[2 * (L_ + tid)]     = v;
        xd[2 * (L_ + tid) + 1] = v;
        __syncthreads();

#pragma unroll 2
        for (int n = 0; n < L_; n++) {
            // (xn, xn) replicated — one aligned LDS.64, broadcast across lanes
            const float2 xnv = *reinterpret_cast<const float2*>(&xd[2 * (L_ + n)]);
            const unsigned long long xn2 = pack2(xnv.x, xnv.y);

            // a2[ip] = (xn*x[n-l1], xn*x[n-l1-1])  -> lanes (l1, l1+1)
            unsigned long long a2[4];
#pragma unroll
            for (int ip = 0; ip < 4; ip++) {
                const int l1 = l1off + 32 * ip;
                const float lo = xs[L_ + n - l1];       // l1
                const float hi = xs[L_ + n - l1 - 1];   // l1+1
                a2[ip] = mul2(xn2, pack2(lo, hi));
            }

            // b2[j] = (xb, xb) replicated — aligned LDS.64 from duplicated array
            unsigned long long b2[8];
#pragma unroll
            for (int j = 0; j < 8; j++) {
                const int l2 = l2_base + tx + 16 * j;
                const float2 xv = *reinterpret_cast<const float2*>(&xd[2 * (L_ + n - l2)]);
                b2[j] = pack2(xv.x, xv.y);
            }

#pragma unroll
            for (int ip = 0; ip < 4; ip++)
#pragma unroll
                for (int j = 0; j < 8; j++)
                    fma2(acc2[ip][j], a2[ip], b2[j]);
        }
    }

    const float scale = 1.0f / (float)(T_ * L_);
    float* ob = out + (size_t)b * L_ * L_;
#pragma unroll
    for (int ip = 0; ip < 4; ip++) {
        const int l1 = l1off + 32 * ip;
#pragma unroll
        for (int j = 0; j < 8; j++) {
            const int l2 = l2_base + tx + 16 * j;
            float lo, hi;
            unpack2(acc2[ip][j], lo, hi);
            ob[l1 * L_ + l2]       = lo * scale;   // l1
            ob[(l1 + 1) * L_ + l2] = hi * scale;   // l1+1
        }
    }
}

extern "C" void kernel_launch(void* const* d_in, const int* in_sizes, int n_in,
                              void* d_out, int out_size)
{
    const float* tgt = (const float*)d_in[0];
    float* out = (float*)d_out;

    dim3 grid(4, B_);
    bispectrum_kernel<<<grid, 256>>>(tgt, out);

    // Reference returns (source, target): echo target after source if the
    // output buffer holds both.
    const long long src_elems = (long long)B_ * L_ * L_;        // 2,097,152
    const long long tgt_elems = (long long)B_ * T_ * L_;        // 65,536
    if ((long long)out_size >= src_elems + tgt_elems) {
        cudaMemcpyAsync(out + src_elems, tgt, sizeof(float) * tgt_elems,
                        cudaMemcpyDeviceToDevice);
    }
}